// round 16
// baseline (speedup 1.0000x reference)
#include <cuda_runtime.h>
#include <cuda_fp16.h>
#include <math.h>
#include <stdint.h>

#define S_ 32
#define B_ 2048
#define M_ 16
#define N_ 8
#define H_ 240
#define IN_ 48
#define O1_ 512
#define ROWS_ (S_ * B_)
#define KC_ 480                 // compacted cat-K: x1 0..239 | h 240..479
typedef __half f16;

// ---------------- scratch ----------------
__device__ __align__(16) f16 g_ch[(size_t)ROWS_ * KC_];
__device__ __align__(16) f16 g_hd[(size_t)ROWS_ * 256];
__device__ __align__(16) f16 g_x2[(size_t)ROWS_ * 512];
__device__ __align__(16) float g_feat[B_ * IN_];
__device__ float g_innov[B_ * N_];
__device__ double g_reg[3];
__device__ __align__(16) f16 g_wb[960 * KC_];
__device__ __align__(16) f16 g_wf1[512 * 256];
__device__ __align__(16) f16 g_wf2[128 * 512];
__device__ float g_bb[960], g_bf1[512], g_bf2[128];

// ---------------- helpers ----------------
__device__ __forceinline__ float cfac_fast(float u, float K10, float inv1mp) {
    float r = __fdividef(u, 1.0f - u);
    float r2 = r * r, r4 = r2 * r2, r5 = r4 * r, r10 = r5 * r5;
    return __fdividef(inv1mp, fmaf(K10, r10, 1.0f));
}
__device__ __forceinline__ float sigm(float x) { return __fdividef(1.0f, 1.0f + __expf(-x)); }
__device__ __forceinline__ float ftanh(float x) {
    float e = __expf(2.0f * x);
    return 1.0f - __fdividef(2.0f, e + 1.0f);
}
__device__ __forceinline__ uint32_t smem_u32(const void* p) {
    uint32_t a;
    asm("{ .reg .u64 t; cvta.to.shared.u64 t, %1; cvt.u32.u64 %0, t; }" : "=r"(a) : "l"(p));
    return a;
}
__device__ __forceinline__ void cp16(uint32_t dst, const void* src) {
    asm volatile("cp.async.cg.shared.global [%0], [%1], 16;" :: "r"(dst), "l"(src));
}
#define CP_COMMIT() asm volatile("cp.async.commit_group;" ::: "memory")
__device__ __forceinline__ void ldm4(uint32_t* r, uint32_t addr) {
    asm volatile("ldmatrix.sync.aligned.m8n8.x4.shared.b16 {%0,%1,%2,%3}, [%4];"
                 : "=r"(r[0]), "=r"(r[1]), "=r"(r[2]), "=r"(r[3]) : "r"(addr));
}
__device__ __forceinline__ void mma16816(float* d, const uint32_t* a, const uint32_t* b) {
    asm volatile(
        "mma.sync.aligned.m16n8k16.row.col.f32.f16.f16.f32 "
        "{%0,%1,%2,%3}, {%4,%5,%6,%7}, {%8,%9}, {%0,%1,%2,%3};"
        : "+f"(d[0]), "+f"(d[1]), "+f"(d[2]), "+f"(d[3])
        : "r"(a[0]), "r"(a[1]), "r"(a[2]), "r"(a[3]), "r"(b[0]), "r"(b[1]));
}

// BK=32 stage: A[128 rows x 32 cols fp16, pitch 80B] = 10240B,
//              B[64 x 32, pitch 80B] at +10240 = 5120B. stage = 15360B.
#define PNL 15360
#define SBIAS_OFF 46080                 // 3-slot ring
#define SMEM_G (SBIAS_OFF + 256)        // 46336 -> 4 CTAs/SM
// k_g1h panel (BK=16 layout, pitch 48)
#define G1PNL 9216
#define SMEM_G1 (4 * G1PNL + 256)

// ---------------------------------------------------------------------------
// Merged weight conversion: one launch does Wbig(960x480) + Wfc1(512x256)
// + Wfc2(128x512), all with padded bias.
// ---------------------------------------------------------------------------
#define WB_N (960 * KC_)
#define WF1_N (512 * 256)
#define WF2_N (128 * 512)
__global__ void k_wall(const float* __restrict__ Wih, const float* __restrict__ bih,
                       const float* __restrict__ Whh, const float* __restrict__ bhh,
                       const float* __restrict__ Wfc1, const float* __restrict__ bfc1,
                       const float* __restrict__ Wfc2, const float* __restrict__ bfc2,
                       f16* __restrict__ Pb, float* __restrict__ bPb,
                       f16* __restrict__ P1, float* __restrict__ bP1,
                       f16* __restrict__ P2, float* __restrict__ bP2) {
    int idx = blockIdx.x * blockDim.x + threadIdx.x;
    if (idx < WB_N) {
        int q = idx / KC_, k = idx - q * KC_;
        int j = q >> 2, t = q & 3;
        float w = 0.0f;
        if (t == 0) {
            w = (k < 240) ? Wih[(size_t)j * 240 + k] : Whh[(size_t)j * 240 + (k - 240)];
        } else if (t == 1) {
            w = (k < 240) ? Wih[(size_t)(240 + j) * 240 + k]
                          : Whh[(size_t)(240 + j) * 240 + (k - 240)];
        } else if (t == 2) {
            if (k < 240) w = Wih[(size_t)(480 + j) * 240 + k];
        } else {
            if (k >= 240) w = Whh[(size_t)(480 + j) * 240 + (k - 240)];
        }
        Pb[idx] = __float2half_rn(w);
        if (k == 0) {
            float b = (t == 0) ? bih[j] + bhh[j]
                    : (t == 1) ? bih[240 + j] + bhh[240 + j]
                    : (t == 2) ? bih[480 + j] : bhh[480 + j];
            bPb[q] = b;
        }
        return;
    }
    int i1 = idx - WB_N;
    if (i1 < WF1_N) {
        int n = i1 >> 8, k = i1 & 255;
        float w = (k < 240) ? Wfc1[(size_t)n * 240 + k] : 0.0f;
        P1[i1] = __float2half_rn(w);
        if (k == 0) bP1[n] = bfc1[n];
        return;
    }
    int i2 = i1 - WF1_N;
    if (i2 < WF2_N) {
        int n = i2 >> 9, k = i2 & 511;
        P2[i2] = __float2half_rn(Wfc2[(size_t)n * 512 + k]);
        if (k == 0) bP2[n] = bfc2[n];
    }
}

// ---------------- prep ----------------
__global__ void k_prep(const float* __restrict__ y_t, const float* __restrict__ x_ens,
                       const float* __restrict__ xppm, const float* __restrict__ xpdm,
                       const float* __restrict__ y_prev, const float* __restrict__ F,
                       const float* __restrict__ Hm,
                       float* __restrict__ feat, float* __restrict__ innov) {
    __shared__ float sF[256], sH[128], sxbar[16][16], sxpm[16][16], sinn[16][8];
    int tid = threadIdx.x;
    if (tid < 256) sF[tid] = F[tid];
    if (tid < 128) sH[tid] = Hm[tid];
    int bl = tid >> 4, m = tid & 15;
    int b = blockIdx.x * 16 + bl;
    float s = 0.0f;
    #pragma unroll 4
    for (int si = 0; si < S_; si++) s += x_ens[((size_t)si * B_ + b) * M_ + m];
    sxbar[bl][m] = s * (1.0f / S_);
    __syncthreads();
    float xp = 0.0f;
    #pragma unroll
    for (int j = 0; j < 16; j++) xp += sF[m * 16 + j] * sxbar[bl][j];
    sxpm[bl][m] = xp;
    __syncthreads();
    if (m < 8) {
        float yp = 0.0f;
        #pragma unroll
        for (int j = 0; j < 16; j++) yp += sH[m * 16 + j] * sxpm[bl][j];
        float inn = y_t[b * N_ + m] - yp;
        sinn[bl][m] = inn;
        innov[b * N_ + m] = inn;
    }
    __syncthreads();
    for (int e = tid; e < 16 * IN_; e += 256) {
        int bb = e / IN_, c = e % IN_;
        int gb = blockIdx.x * 16 + bb;
        float v;
        if (c < 16)      v = sxbar[bb][c]      - xpdm[gb * M_ + c];
        else if (c < 24) v = sinn[bb][c - 16];
        else if (c < 40) v = sxbar[bb][c - 24] - xppm[gb * M_ + (c - 24)];
        else             v = y_t[gb * N_ + (c - 40)] - y_prev[gb * N_ + (c - 40)];
        feat[gb * IN_ + c] = v;
    }
}

// ---------------------------------------------------------------------------
// fp16 HMMA GEMM (R11/R15-proven pipeline). CTA 128x64, warps 4x2, BK=32,
// 3-slot ring, distance-2 prefetch, one __syncthreads per 32 MMAs, 4 CTAs/SM.
// EPI: 2 relu*cdrop -> fp16; 3 fused GRU+dropout -> hd; 4 fused Kalman out
// ---------------------------------------------------------------------------
template <int EPI>
__global__ void __launch_bounds__(256, 4) mma_gemm(
    const f16* __restrict__ A, int Kpad,
    const f16* __restrict__ W,
    const float* __restrict__ biasp,
    float* __restrict__ outF, int Ostride,
    f16* __restrict__ O,
    const float* __restrict__ u_outp, const float* __restrict__ p_outp,
    const float* __restrict__ h_ens, const float* __restrict__ u_fc1,
    const float* __restrict__ x_ens, const float* __restrict__ Fm,
    const float* __restrict__ innov) {
    extern __shared__ char smem[];
    const uint32_t su = smem_u32(smem);
    const int tid = threadIdx.x;
    const int lane = tid & 31;
    const int wm = (tid >> 5) & 3;
    const int wn = tid >> 7;
    const int n0 = blockIdx.x * 64;
    const int row0 = blockIdx.y * 128;
    const int NK2 = Kpad >> 5;
    const int ar = tid >> 1, acg = tid & 1;
    const int br = tid >> 1, bcg = tid & 1;

    float* sBias = (float*)(smem + SBIAS_OFF);
    if (tid < 64) sBias[tid] = biasp[n0 + tid];

    #define LOADSTG(slot, kc2) do { \
        uint32_t sb = su + (slot) * PNL; \
        int kk = (kc2) * 32 + acg * 16; \
        const f16* ap = A + (size_t)(row0 + ar) * Kpad + kk; \
        cp16(sb + ar * 80 + acg * 32, ap); \
        cp16(sb + ar * 80 + acg * 32 + 16, ap + 8); \
        if (tid < 128) { \
            const f16* wp = W + (size_t)(n0 + br) * Kpad + (kc2) * 32 + bcg * 16; \
            cp16(sb + 10240 + br * 80 + bcg * 32, wp); \
            cp16(sb + 10240 + br * 80 + bcg * 32 + 16, wp + 8); \
        } \
        CP_COMMIT(); \
    } while (0)

    float d[2][4][4];
    #pragma unroll
    for (int i = 0; i < 2; i++)
        #pragma unroll
        for (int j = 0; j < 4; j++)
            #pragma unroll
            for (int k = 0; k < 4; k++) d[i][j][k] = 0.0f;

    const uint32_t a_off = (wm * 32 + (lane & 15)) * 80 + (lane >> 4) * 16;
    const uint32_t b_off = (wn * 32 + (lane & 7) + ((lane >> 4) << 3)) * 80 + (((lane >> 3) & 1) << 4);

    LOADSTG(0, 0);
    LOADSTG(1, 1);
    for (int kc2 = 0; kc2 < NK2; kc2++) {
        if (kc2 + 1 < NK2) asm volatile("cp.async.wait_group 1;" ::: "memory");
        else               asm volatile("cp.async.wait_group 0;" ::: "memory");
        __syncthreads();
        if (kc2 + 2 < NK2) LOADSTG((kc2 + 2) % 3, kc2 + 2);
        uint32_t pb = su + (kc2 % 3) * PNL;
        #pragma unroll
        for (int s = 0; s < 2; s++) {
            uint32_t soff = s * 32;
            uint32_t a[2][4], b[4][2], q[4];
            #pragma unroll
            for (int mt = 0; mt < 2; mt++) ldm4(a[mt], pb + a_off + soff + mt * 1280);
            #pragma unroll
            for (int pp = 0; pp < 2; pp++) {
                ldm4(q, pb + 10240 + b_off + soff + pp * 1280);
                b[pp * 2][0] = q[0]; b[pp * 2][1] = q[1];
                b[pp * 2 + 1][0] = q[2]; b[pp * 2 + 1][1] = q[3];
            }
            #pragma unroll
            for (int mt = 0; mt < 2; mt++)
                #pragma unroll
                for (int nt = 0; nt < 4; nt++)
                    mma16816(d[mt][nt], a[mt], b[nt]);
        }
    }
    #undef LOADSTG

    __syncthreads();
    // ---- two-pass epilogue over row halves (stage 64x65 fp32 in ring) ----
    float* stage = (float*)smem;
    float* sXe  = (float*)(smem + 16640);
    float* sInn = (float*)(smem + 20736);
    float* sF   = (float*)(smem + 22784);

    float pout = 0.0f, fout = 0.0f, K10 = 0.0f;
    if (EPI == 2 || EPI == 3) {
        pout = *p_outp;
        fout = 1.0f + __expf(pout);
        K10 = __expf(10.0f * pout);
    }

    #pragma unroll
    for (int h = 0; h < 2; h++) {
        if (h) __syncthreads();
        if ((wm >> 1) == h) {
            int wml = wm & 1;
            int lr = lane >> 2, lc = (lane & 3) * 2;
            #pragma unroll
            for (int mt = 0; mt < 2; mt++)
                #pragma unroll
                for (int nt = 0; nt < 4; nt++) {
                    int rr = wml * 32 + mt * 16 + lr;
                    int cc = wn * 32 + nt * 8 + lc;
                    stage[rr * 65 + cc] = d[mt][nt][0];
                    stage[rr * 65 + cc + 1] = d[mt][nt][1];
                    stage[(rr + 8) * 65 + cc] = d[mt][nt][2];
                    stage[(rr + 8) * 65 + cc + 1] = d[mt][nt][3];
                }
        }
        int rbase = row0 + h * 64;
        if (EPI == 4) {
            for (int i = tid; i < 64 * 16; i += 256) sXe[i] = x_ens[(size_t)rbase * 16 + i];
            int b0 = rbase & (B_ - 1);
            for (int i = tid; i < 64 * 8; i += 256) sInn[i] = innov[(size_t)b0 * 8 + i];
            if (tid < 256) sF[tid] = Fm[tid];
        }
        __syncthreads();

        if (EPI == 2) {
            // 4 cols per iteration, float4 u-loads
            for (int i = tid; i < 64 * 16; i += 256) {
                int r = i >> 4, c = (i & 15) * 4;
                int row = rbase + r;
                float v0 = fmaxf(stage[r * 65 + c] + sBias[c], 0.0f);
                float v1 = fmaxf(stage[r * 65 + c + 1] + sBias[c + 1], 0.0f);
                float v2 = fmaxf(stage[r * 65 + c + 2] + sBias[c + 2], 0.0f);
                float v3 = fmaxf(stage[r * 65 + c + 3] + sBias[c + 3], 0.0f);
                float4 uu = *(const float4*)(u_outp + (size_t)row * Ostride + n0 + c);
                v0 *= cfac_fast(uu.x, K10, fout);
                v1 *= cfac_fast(uu.y, K10, fout);
                v2 *= cfac_fast(uu.z, K10, fout);
                v3 *= cfac_fast(uu.w, K10, fout);
                __half2 p0, p1;
                p0.x = __float2half_rn(v0); p0.y = __float2half_rn(v1);
                p1.x = __float2half_rn(v2); p1.y = __float2half_rn(v3);
                f16* op = O + (size_t)row * Ostride + n0 + c;
                *(__half2*)op = p0;
                *(__half2*)(op + 2) = p1;
            }
        } else if (EPI == 3) {
            int j0 = n0 >> 2;
            for (int i = tid; i < 64 * 16; i += 256) {
                int r = i >> 4, jj = i & 15;
                int jg = j0 + jj;
                int row = rbase + r;
                float a   = stage[r * 65 + 4 * jj]     + sBias[4 * jj];
                float b   = stage[r * 65 + 4 * jj + 1] + sBias[4 * jj + 1];
                float in_ = stage[r * 65 + 4 * jj + 2] + sBias[4 * jj + 2];
                float hn  = stage[r * 65 + 4 * jj + 3] + sBias[4 * jj + 3];
                float rg = sigm(a), z = sigm(b);
                float ng = ftanh(in_ + rg * hn);
                float hv = h_ens[(size_t)row * H_ + jg];
                float hnew = (1.0f - z) * ng + z * hv;
                float v = hnew * cfac_fast(u_fc1[(size_t)row * H_ + jg], K10, fout);
                O[(size_t)row * 256 + jg] = __float2half_rn(v);
            }
        } else {   // EPI == 4: fused Kalman. cols n0..n0+63 = m (n0/8..n0/8+7)
            int m0 = n0 >> 3;
            for (int i = tid; i < 64 * 8; i += 256) {
                int r = i >> 3, mm = i & 7;
                int m = m0 + mm;
                float acc = 0.0f;
                #pragma unroll
                for (int j = 0; j < 16; j++) acc += sF[m * 16 + j] * sXe[r * 16 + j];
                #pragma unroll
                for (int n = 0; n < 8; n++)
                    acc += (stage[r * 65 + mm * 8 + n] + sBias[mm * 8 + n]) * sInn[r * 8 + n];
                outF[(size_t)(rbase + r) * 16 + m] = acc;
            }
        }
    }
    if (EPI == 3 && (n0 >> 2) == 224) {   // zero hd pad cols 240..255
        f16 zz = __float2half_rn(0.0f);
        for (int i = tid; i < 128 * 16; i += 256)
            O[(size_t)(row0 + (i >> 4)) * 256 + 240 + (i & 15)] = zz;
    }
}

// ---------------------------------------------------------------------------
// k_g1h: grid (8, 512). bx<4: x1 tile -> ch cols 0..239 (guarded);
// bx>=4: h_ens copy (float4 vectorized) -> ch cols 240..479
// ---------------------------------------------------------------------------
__global__ void __launch_bounds__(256) k_g1h(
    const float* __restrict__ feat, const float* __restrict__ u_in,
    const float* __restrict__ p_inp,
    const float* __restrict__ W_in, const float* __restrict__ b_in,
    const float* __restrict__ h_ens,
    f16* __restrict__ C) {
    extern __shared__ char smem[];
    const int tid = threadIdx.x;
    const int row0 = blockIdx.y * 128;

    if (blockIdx.x >= 4) {
        int c0 = (blockIdx.x - 4) * 64;
        for (int i = tid; i < 128 * 16; i += 256) {
            int r = i >> 4, c = c0 + (i & 15) * 4;
            if (c >= 240) continue;
            int row = row0 + r;
            float4 hv = *(const float4*)(h_ens + (size_t)row * H_ + c);
            __half2 p0, p1;
            p0.x = __float2half_rn(hv.x); p0.y = __float2half_rn(hv.y);
            p1.x = __float2half_rn(hv.z); p1.y = __float2half_rn(hv.w);
            f16* op = C + (size_t)row * KC_ + 240 + c;
            *(__half2*)op = p0;
            *(__half2*)(op + 2) = p1;
        }
        return;
    }

    const uint32_t su = smem_u32(smem);
    const int lane = tid & 31;
    const int wm = (tid >> 5) & 3;
    const int wn = tid >> 7;
    const int n0 = blockIdx.x * 64;
    float* sBias = (float*)(smem + 4 * G1PNL);
    if (tid < 64) sBias[tid] = (n0 + tid < 240) ? b_in[n0 + tid] : 0.0f;

    for (int i = tid; i < 64 * 64; i += 256) {
        int n = i >> 6, k = i & 63;
        float w = (n0 + n < 240 && k < IN_) ? W_in[(size_t)(n0 + n) * IN_ + k] : 0.0f;
        uint32_t pb = (k >> 4) * G1PNL + 6144 + n * 48 + (k & 15) * 2;
        *(f16*)(smem + pb) = __float2half_rn(w);
    }
    {
        float plog = *p_inp;
        float finv = 1.0f + __expf(plog);
        float K10 = __expf(10.0f * plog);
        for (int i = tid; i < 128 * 64; i += 256) {
            int r = i >> 6, c = i & 63;
            float v = 0.0f;
            if (c < IN_) {
                int b = (row0 + r) & (B_ - 1);
                v = feat[b * IN_ + c] *
                    cfac_fast(u_in[(size_t)(row0 + r) * IN_ + c], K10, finv);
            }
            uint32_t pb = (c >> 4) * G1PNL + r * 48 + (c & 15) * 2;
            *(f16*)(smem + pb) = __float2half_rn(v);
        }
    }
    __syncthreads();

    float d[2][4][4];
    #pragma unroll
    for (int i = 0; i < 2; i++)
        #pragma unroll
        for (int j = 0; j < 4; j++)
            #pragma unroll
            for (int k = 0; k < 4; k++) d[i][j][k] = 0.0f;
    const uint32_t a_off = (wm * 32 + (lane & 15)) * 48 + (lane >> 4) * 16;
    const uint32_t b_off = (wn * 32 + (lane & 7) + ((lane >> 4) << 3)) * 48 + (((lane >> 3) & 1) << 4);
    #pragma unroll
    for (int p = 0; p < 4; p++) {
        uint32_t pb = su + p * G1PNL;
        uint32_t a[2][4], b[4][2], q[4];
        #pragma unroll
        for (int mt = 0; mt < 2; mt++) ldm4(a[mt], pb + a_off + mt * 768);
        #pragma unroll
        for (int pp = 0; pp < 2; pp++) {
            ldm4(q, pb + 6144 + b_off + pp * 768);
            b[pp * 2][0] = q[0]; b[pp * 2][1] = q[1];
            b[pp * 2 + 1][0] = q[2]; b[pp * 2 + 1][1] = q[3];
        }
        #pragma unroll
        for (int mt = 0; mt < 2; mt++)
            #pragma unroll
            for (int nt = 0; nt < 4; nt++)
                mma16816(d[mt][nt], a[mt], b[nt]);
    }
    __syncthreads();
    float* stage = (float*)smem;
    {
        int lr = lane >> 2, lc = (lane & 3) * 2;
        #pragma unroll
        for (int mt = 0; mt < 2; mt++)
            #pragma unroll
            for (int nt = 0; nt < 4; nt++) {
                int rr = wm * 32 + mt * 16 + lr;
                int cc = wn * 32 + nt * 8 + lc;
                stage[rr * 65 + cc] = d[mt][nt][0];
                stage[rr * 65 + cc + 1] = d[mt][nt][1];
                stage[(rr + 8) * 65 + cc] = d[mt][nt][2];
                stage[(rr + 8) * 65 + cc + 1] = d[mt][nt][3];
            }
    }
    __syncthreads();
    for (int i = tid; i < 128 * 32; i += 256) {
        int r = i >> 5, c = (i & 31) * 2;
        if (n0 + c >= 240) continue;
        float v0 = fmaxf(stage[r * 65 + c] + sBias[c], 0.0f);
        float v1 = fmaxf(stage[r * 65 + c + 1] + sBias[c + 1], 0.0f);
        __half2 pv;
        pv.x = __float2half_rn(v0);
        pv.y = __float2half_rn(v1);
        *(__half2*)(C + (size_t)(row0 + r) * KC_ + n0 + c) = pv;
    }
}

// ---------------- regularizer ----------------
__global__ void k_reg_sums(const float* __restrict__ W_in, const float* __restrict__ W_fc1,
                           const float* __restrict__ W_fc2, double* __restrict__ reg) {
    __shared__ double sd[256];
    int l = blockIdx.x;
    const float* W = (l == 0) ? W_in : (l == 1) ? W_fc1 : W_fc2;
    int n = (l == 0) ? H_ * IN_ : (l == 1) ? O1_ * H_ : M_ * N_ * O1_;
    double s = 0.0;
    for (int i = threadIdx.x; i < n; i += 256) { float w = W[i]; s += (double)w * (double)w; }
    sd[threadIdx.x] = s;
    __syncthreads();
    for (int o = 128; o > 0; o >>= 1) {
        if (threadIdx.x < o) sd[threadIdx.x] += sd[threadIdx.x + o];
        __syncthreads();
    }
    if (threadIdx.x == 0) reg[l] = sd[0];
}
__global__ void k_reg_final(const double* __restrict__ reg, const float* __restrict__ p_in,
                            const float* __restrict__ p_fc1, const float* __restrict__ p_fc2,
                            float* __restrict__ out_reg) {
    double tot = 0.0;
    float pl[3] = {*p_in, *p_fc1, *p_fc2};
    double fan[3] = {(double)IN_, (double)H_, (double)O1_};
    #pragma unroll
    for (int l = 0; l < 3; l++) {
        double p = 1.0 / (1.0 + exp(-(double)pl[l]));
        tot += reg[l] / (1.0 - p) + fan[l] * (p * log(p) + (1.0 - p) * log1p(-p));
    }
    if (threadIdx.x < S_) out_reg[threadIdx.x] = (float)tot;
}

// ---------------- launch ----------------
extern "C" void kernel_launch(void* const* d_in, const int* in_sizes, int n_in,
                              void* d_out, int out_size) {
    const float* y_t    = (const float*)d_in[0];
    const float* x_ens  = (const float*)d_in[1];
    const float* xppm   = (const float*)d_in[2];
    const float* xpdm   = (const float*)d_in[3];
    const float* y_prev = (const float*)d_in[4];
    const float* h_ens  = (const float*)d_in[5];
    const float* F      = (const float*)d_in[6];
    const float* Hm     = (const float*)d_in[7];
    const float* W_in   = (const float*)d_in[8];
    const float* b_in   = (const float*)d_in[9];
    const float* W_ih   = (const float*)d_in[10];
    const float* b_ih   = (const float*)d_in[11];
    const float* W_hh   = (const float*)d_in[12];
    const float* b_hh   = (const float*)d_in[13];
    const float* W_fc1  = (const float*)d_in[14];
    const float* b_fc1  = (const float*)d_in[15];
    const float* W_fc2  = (const float*)d_in[16];
    const float* b_fc2  = (const float*)d_in[17];
    const float* p_in   = (const float*)d_in[18];
    const float* p_fc1  = (const float*)d_in[19];
    const float* p_fc2  = (const float*)d_in[20];
    const float* u_in   = (const float*)d_in[21];
    const float* u_fc1  = (const float*)d_in[22];
    const float* u_fc2  = (const float*)d_in[23];
    float* out = (float*)d_out;

    cudaFuncSetAttribute(mma_gemm<2>, cudaFuncAttributeMaxDynamicSharedMemorySize, SMEM_G);
    cudaFuncSetAttribute(mma_gemm<3>, cudaFuncAttributeMaxDynamicSharedMemorySize, SMEM_G);
    cudaFuncSetAttribute(mma_gemm<4>, cudaFuncAttributeMaxDynamicSharedMemorySize, SMEM_G);
    cudaFuncSetAttribute(k_g1h, cudaFuncAttributeMaxDynamicSharedMemorySize, SMEM_G1);

    float *featp, *innp, *bbp, *bf1p, *bf2p;
    double* regp;
    f16 *ch, *hd, *x2, *wb, *wf1, *wf2;
    cudaGetSymbolAddress((void**)&featp, g_feat);
    cudaGetSymbolAddress((void**)&innp, g_innov);
    cudaGetSymbolAddress((void**)&regp, g_reg);
    cudaGetSymbolAddress((void**)&ch, g_ch);
    cudaGetSymbolAddress((void**)&hd, g_hd);
    cudaGetSymbolAddress((void**)&x2, g_x2);
    cudaGetSymbolAddress((void**)&wb, g_wb);
    cudaGetSymbolAddress((void**)&wf1, g_wf1);
    cudaGetSymbolAddress((void**)&wf2, g_wf2);
    cudaGetSymbolAddress((void**)&bbp, g_bb);
    cudaGetSymbolAddress((void**)&bf1p, g_bf1);
    cudaGetSymbolAddress((void**)&bf2p, g_bf2);

    // merged weight conversion (1 launch replaces 3)
    k_wall<<<(WB_N + WF1_N + WF2_N + 255) / 256, 256>>>(
        W_ih, b_ih, W_hh, b_hh, W_fc1, b_fc1, W_fc2, b_fc2,
        wb, bbp, wf1, bf1p, wf2, bf2p);
    k_prep<<<B_ / 16, 256>>>(y_t, x_ens, xppm, xpdm, y_prev, F, Hm, featp, innp);
    k_g1h<<<dim3(8, ROWS_ / 128), 256, SMEM_G1>>>(featp, u_in, p_in, W_in, b_in, h_ens, ch);
    // fused gi+gh+GRU+dropout -> hd  (K compacted to 480)
    mma_gemm<3><<<dim3(15, ROWS_ / 128), 256, SMEM_G>>>(
        ch, KC_, wb, bbp, nullptr, 0, hd, nullptr, p_fc1, h_ens, u_fc1,
        nullptr, nullptr, nullptr);
    // x2 = cdrop(relu(hd @ W_fc1^T + b_fc1), u_fc2)
    mma_gemm<2><<<dim3(8, ROWS_ / 128), 256, SMEM_G>>>(
        hd, 256, wf1, bf1p, nullptr, 512, x2, u_fc2, p_fc2, nullptr, nullptr,
        nullptr, nullptr, nullptr);
    // Kv = x2 @ W_fc2^T + b_fc2, fused Kalman -> x_filt
    mma_gemm<4><<<dim3(2, ROWS_ / 128), 256, SMEM_G>>>(
        x2, 512, wf2, bf2p, out, 16, nullptr, nullptr, nullptr, nullptr, nullptr,
        x_ens, F, innp);
    k_reg_sums<<<3, 256>>>(W_in, W_fc1, W_fc2, regp);
    k_reg_final<<<1, 32>>>(regp, p_in, p_fc1, p_fc2, out + (size_t)ROWS_ * M_);
}

// round 17
// speedup vs baseline: 1.4720x; 1.4720x over previous
#include <cuda_runtime.h>
#include <cuda_fp16.h>
#include <math.h>
#include <stdint.h>

#define S_ 32
#define B_ 2048
#define M_ 16
#define N_ 8
#define H_ 240
#define IN_ 48
#define O1_ 512
#define ROWS_ (S_ * B_)
#define KC_ 480                 // compacted cat-K: x1 0..239 | h 240..479
typedef __half f16;

// ---------------- scratch ----------------
__device__ __align__(16) f16 g_ch[(size_t)ROWS_ * KC_];
__device__ __align__(16) f16 g_hd[(size_t)ROWS_ * 256];
__device__ __align__(16) f16 g_x2[(size_t)ROWS_ * 512];
__device__ __align__(16) float g_feat[B_ * IN_];
__device__ float g_innov[B_ * N_];
__device__ double g_reg[3];
__device__ __align__(16) f16 g_wb[960 * KC_];
__device__ __align__(16) f16 g_wf1[512 * 256];
__device__ __align__(16) f16 g_wf2[128 * 512];
__device__ float g_bb[960], g_bf1[512], g_bf2[128];

// ---------------- helpers ----------------
__device__ __forceinline__ float cfac_fast(float u, float K10, float inv1mp) {
    float r = __fdividef(u, 1.0f - u);
    float r2 = r * r, r4 = r2 * r2, r5 = r4 * r, r10 = r5 * r5;
    return __fdividef(inv1mp, fmaf(K10, r10, 1.0f));
}
__device__ __forceinline__ float sigm(float x) { return __fdividef(1.0f, 1.0f + __expf(-x)); }
__device__ __forceinline__ float ftanh(float x) {
    float e = __expf(2.0f * x);
    return 1.0f - __fdividef(2.0f, e + 1.0f);
}
__device__ __forceinline__ uint32_t smem_u32(const void* p) {
    uint32_t a;
    asm("{ .reg .u64 t; cvta.to.shared.u64 t, %1; cvt.u32.u64 %0, t; }" : "=r"(a) : "l"(p));
    return a;
}
__device__ __forceinline__ void cp16(uint32_t dst, const void* src) {
    asm volatile("cp.async.cg.shared.global [%0], [%1], 16;" :: "r"(dst), "l"(src));
}
#define CP_COMMIT() asm volatile("cp.async.commit_group;" ::: "memory")
__device__ __forceinline__ void ldm4(uint32_t* r, uint32_t addr) {
    asm volatile("ldmatrix.sync.aligned.m8n8.x4.shared.b16 {%0,%1,%2,%3}, [%4];"
                 : "=r"(r[0]), "=r"(r[1]), "=r"(r[2]), "=r"(r[3]) : "r"(addr));
}
__device__ __forceinline__ void mma16816(float* d, const uint32_t* a, const uint32_t* b) {
    asm volatile(
        "mma.sync.aligned.m16n8k16.row.col.f32.f16.f16.f32 "
        "{%0,%1,%2,%3}, {%4,%5,%6,%7}, {%8,%9}, {%0,%1,%2,%3};"
        : "+f"(d[0]), "+f"(d[1]), "+f"(d[2]), "+f"(d[3])
        : "r"(a[0]), "r"(a[1]), "r"(a[2]), "r"(a[3]), "r"(b[0]), "r"(b[1]));
}

// BK=32 stage: A[128 rows x 32 cols fp16, pitch 80B] = 10240B,
//              B[64 x 32, pitch 80B] at +10240 = 5120B. stage = 15360B.
#define PNL 15360
#define SBIAS_OFF 46080                 // 3-slot ring
#define SMEM_G (SBIAS_OFF + 256)        // 46336 -> 4 CTAs/SM
// k_g1h panel (BK=16 layout, pitch 48)
#define G1PNL 9216
#define SMEM_G1 (4 * G1PNL + 256)

// ---------------------------------------------------------------------------
// Merged weight conversion: one launch does Wbig(960x480) + Wfc1(512x256)
// + Wfc2(128x512), all with padded bias.
// ---------------------------------------------------------------------------
#define WB_N (960 * KC_)
#define WF1_N (512 * 256)
#define WF2_N (128 * 512)
__global__ void k_wall(const float* __restrict__ Wih, const float* __restrict__ bih,
                       const float* __restrict__ Whh, const float* __restrict__ bhh,
                       const float* __restrict__ Wfc1, const float* __restrict__ bfc1,
                       const float* __restrict__ Wfc2, const float* __restrict__ bfc2,
                       f16* __restrict__ Pb, float* __restrict__ bPb,
                       f16* __restrict__ P1, float* __restrict__ bP1,
                       f16* __restrict__ P2, float* __restrict__ bP2) {
    int idx = blockIdx.x * blockDim.x + threadIdx.x;
    if (idx < WB_N) {
        int q = idx / KC_, k = idx - q * KC_;
        int j = q >> 2, t = q & 3;
        float w = 0.0f;
        if (t == 0) {
            w = (k < 240) ? Wih[(size_t)j * 240 + k] : Whh[(size_t)j * 240 + (k - 240)];
        } else if (t == 1) {
            w = (k < 240) ? Wih[(size_t)(240 + j) * 240 + k]
                          : Whh[(size_t)(240 + j) * 240 + (k - 240)];
        } else if (t == 2) {
            if (k < 240) w = Wih[(size_t)(480 + j) * 240 + k];
        } else {
            if (k >= 240) w = Whh[(size_t)(480 + j) * 240 + (k - 240)];
        }
        Pb[idx] = __float2half_rn(w);
        if (k == 0) {
            float b = (t == 0) ? bih[j] + bhh[j]
                    : (t == 1) ? bih[240 + j] + bhh[240 + j]
                    : (t == 2) ? bih[480 + j] : bhh[480 + j];
            bPb[q] = b;
        }
        return;
    }
    int i1 = idx - WB_N;
    if (i1 < WF1_N) {
        int n = i1 >> 8, k = i1 & 255;
        float w = (k < 240) ? Wfc1[(size_t)n * 240 + k] : 0.0f;
        P1[i1] = __float2half_rn(w);
        if (k == 0) bP1[n] = bfc1[n];
        return;
    }
    int i2 = i1 - WF1_N;
    if (i2 < WF2_N) {
        int n = i2 >> 9, k = i2 & 511;
        P2[i2] = __float2half_rn(Wfc2[(size_t)n * 512 + k]);
        if (k == 0) bP2[n] = bfc2[n];
    }
}

// ---------------- prep ----------------
__global__ void k_prep(const float* __restrict__ y_t, const float* __restrict__ x_ens,
                       const float* __restrict__ xppm, const float* __restrict__ xpdm,
                       const float* __restrict__ y_prev, const float* __restrict__ F,
                       const float* __restrict__ Hm,
                       float* __restrict__ feat, float* __restrict__ innov) {
    __shared__ float sF[256], sH[128], sxbar[16][16], sxpm[16][16], sinn[16][8];
    int tid = threadIdx.x;
    if (tid < 256) sF[tid] = F[tid];
    if (tid < 128) sH[tid] = Hm[tid];
    int bl = tid >> 4, m = tid & 15;
    int b = blockIdx.x * 16 + bl;
    float s = 0.0f;
    #pragma unroll 4
    for (int si = 0; si < S_; si++) s += x_ens[((size_t)si * B_ + b) * M_ + m];
    sxbar[bl][m] = s * (1.0f / S_);
    __syncthreads();
    float xp = 0.0f;
    #pragma unroll
    for (int j = 0; j < 16; j++) xp += sF[m * 16 + j] * sxbar[bl][j];
    sxpm[bl][m] = xp;
    __syncthreads();
    if (m < 8) {
        float yp = 0.0f;
        #pragma unroll
        for (int j = 0; j < 16; j++) yp += sH[m * 16 + j] * sxpm[bl][j];
        float inn = y_t[b * N_ + m] - yp;
        sinn[bl][m] = inn;
        innov[b * N_ + m] = inn;
    }
    __syncthreads();
    for (int e = tid; e < 16 * IN_; e += 256) {
        int bb = e / IN_, c = e % IN_;
        int gb = blockIdx.x * 16 + bb;
        float v;
        if (c < 16)      v = sxbar[bb][c]      - xpdm[gb * M_ + c];
        else if (c < 24) v = sinn[bb][c - 16];
        else if (c < 40) v = sxbar[bb][c - 24] - xppm[gb * M_ + (c - 24)];
        else             v = y_t[gb * N_ + (c - 40)] - y_prev[gb * N_ + (c - 40)];
        feat[gb * IN_ + c] = v;
    }
}

// ---------------------------------------------------------------------------
// fp16 HMMA GEMM (R11/R15-proven pipeline). CTA 128x64, warps 4x2, BK=32,
// 3-slot ring, distance-2 prefetch, one __syncthreads per 32 MMAs, 4 CTAs/SM.
// EPI: 2 relu*cdrop -> fp16; 3 fused GRU+dropout -> hd; 4 fused Kalman out
// ---------------------------------------------------------------------------
template <int EPI>
__global__ void __launch_bounds__(256, 4) mma_gemm(
    const f16* __restrict__ A, int Kpad,
    const f16* __restrict__ W,
    const float* __restrict__ biasp,
    float* __restrict__ outF, int Ostride,
    f16* __restrict__ O,
    const float* __restrict__ u_outp, const float* __restrict__ p_outp,
    const float* __restrict__ h_ens, const float* __restrict__ u_fc1,
    const float* __restrict__ x_ens, const float* __restrict__ Fm,
    const float* __restrict__ innov) {
    extern __shared__ char smem[];
    const uint32_t su = smem_u32(smem);
    const int tid = threadIdx.x;
    const int lane = tid & 31;
    const int wm = (tid >> 5) & 3;
    const int wn = tid >> 7;
    const int n0 = blockIdx.x * 64;
    const int row0 = blockIdx.y * 128;
    const int NK2 = Kpad >> 5;
    const int ar = tid >> 1, acg = tid & 1;
    const int br = tid >> 1, bcg = tid & 1;

    float* sBias = (float*)(smem + SBIAS_OFF);
    if (tid < 64) sBias[tid] = biasp[n0 + tid];

    #define LOADSTG(slot, kc2) do { \
        uint32_t sb = su + (slot) * PNL; \
        int kk = (kc2) * 32 + acg * 16; \
        const f16* ap = A + (size_t)(row0 + ar) * Kpad + kk; \
        cp16(sb + ar * 80 + acg * 32, ap); \
        cp16(sb + ar * 80 + acg * 32 + 16, ap + 8); \
        if (tid < 128) { \
            const f16* wp = W + (size_t)(n0 + br) * Kpad + (kc2) * 32 + bcg * 16; \
            cp16(sb + 10240 + br * 80 + bcg * 32, wp); \
            cp16(sb + 10240 + br * 80 + bcg * 32 + 16, wp + 8); \
        } \
        CP_COMMIT(); \
    } while (0)

    float d[2][4][4];
    #pragma unroll
    for (int i = 0; i < 2; i++)
        #pragma unroll
        for (int j = 0; j < 4; j++)
            #pragma unroll
            for (int k = 0; k < 4; k++) d[i][j][k] = 0.0f;

    const uint32_t a_off = (wm * 32 + (lane & 15)) * 80 + (lane >> 4) * 16;
    const uint32_t b_off = (wn * 32 + (lane & 7) + ((lane >> 4) << 3)) * 80 + (((lane >> 3) & 1) << 4);

    LOADSTG(0, 0);
    LOADSTG(1, 1);
    for (int kc2 = 0; kc2 < NK2; kc2++) {
        if (kc2 + 1 < NK2) asm volatile("cp.async.wait_group 1;" ::: "memory");
        else               asm volatile("cp.async.wait_group 0;" ::: "memory");
        __syncthreads();
        if (kc2 + 2 < NK2) LOADSTG((kc2 + 2) % 3, kc2 + 2);
        uint32_t pb = su + (kc2 % 3) * PNL;
        #pragma unroll
        for (int s = 0; s < 2; s++) {
            uint32_t soff = s * 32;
            uint32_t a[2][4], b[4][2], q[4];
            #pragma unroll
            for (int mt = 0; mt < 2; mt++) ldm4(a[mt], pb + a_off + soff + mt * 1280);
            #pragma unroll
            for (int pp = 0; pp < 2; pp++) {
                ldm4(q, pb + 10240 + b_off + soff + pp * 1280);
                b[pp * 2][0] = q[0]; b[pp * 2][1] = q[1];
                b[pp * 2 + 1][0] = q[2]; b[pp * 2 + 1][1] = q[3];
            }
            #pragma unroll
            for (int mt = 0; mt < 2; mt++)
                #pragma unroll
                for (int nt = 0; nt < 4; nt++)
                    mma16816(d[mt][nt], a[mt], b[nt]);
        }
    }
    #undef LOADSTG

    __syncthreads();
    // ---- two-pass epilogue over row halves (stage 64x65 fp32 in ring) ----
    float* stage = (float*)smem;
    float* sXe  = (float*)(smem + 16640);
    float* sInn = (float*)(smem + 20736);
    float* sF   = (float*)(smem + 22784);

    float pout = 0.0f, fout = 0.0f, K10 = 0.0f;
    if (EPI == 2 || EPI == 3) {
        pout = *p_outp;
        fout = 1.0f + __expf(pout);
        K10 = __expf(10.0f * pout);
    }

    #pragma unroll
    for (int h = 0; h < 2; h++) {
        if (h) __syncthreads();
        if ((wm >> 1) == h) {
            int wml = wm & 1;
            int lr = lane >> 2, lc = (lane & 3) * 2;
            #pragma unroll
            for (int mt = 0; mt < 2; mt++)
                #pragma unroll
                for (int nt = 0; nt < 4; nt++) {
                    int rr = wml * 32 + mt * 16 + lr;
                    int cc = wn * 32 + nt * 8 + lc;
                    stage[rr * 65 + cc] = d[mt][nt][0];
                    stage[rr * 65 + cc + 1] = d[mt][nt][1];
                    stage[(rr + 8) * 65 + cc] = d[mt][nt][2];
                    stage[(rr + 8) * 65 + cc + 1] = d[mt][nt][3];
                }
        }
        int rbase = row0 + h * 64;
        if (EPI == 4) {
            for (int i = tid; i < 64 * 16; i += 256) sXe[i] = x_ens[(size_t)rbase * 16 + i];
            int b0 = rbase & (B_ - 1);
            for (int i = tid; i < 64 * 8; i += 256) sInn[i] = innov[(size_t)b0 * 8 + i];
            if (tid < 256) sF[tid] = Fm[tid];
        }
        __syncthreads();

        if (EPI == 2) {
            for (int i = tid; i < 64 * 16; i += 256) {
                int r = i >> 4, c = (i & 15) * 4;
                int row = rbase + r;
                float v0 = fmaxf(stage[r * 65 + c] + sBias[c], 0.0f);
                float v1 = fmaxf(stage[r * 65 + c + 1] + sBias[c + 1], 0.0f);
                float v2 = fmaxf(stage[r * 65 + c + 2] + sBias[c + 2], 0.0f);
                float v3 = fmaxf(stage[r * 65 + c + 3] + sBias[c + 3], 0.0f);
                float4 uu = *(const float4*)(u_outp + (size_t)row * Ostride + n0 + c);
                v0 *= cfac_fast(uu.x, K10, fout);
                v1 *= cfac_fast(uu.y, K10, fout);
                v2 *= cfac_fast(uu.z, K10, fout);
                v3 *= cfac_fast(uu.w, K10, fout);
                __half2 p0, p1;
                p0.x = __float2half_rn(v0); p0.y = __float2half_rn(v1);
                p1.x = __float2half_rn(v2); p1.y = __float2half_rn(v3);
                f16* op = O + (size_t)row * Ostride + n0 + c;
                *(__half2*)op = p0;
                *(__half2*)(op + 2) = p1;
            }
        } else if (EPI == 3) {
            int j0 = n0 >> 2;
            for (int i = tid; i < 64 * 16; i += 256) {
                int r = i >> 4, jj = i & 15;
                int jg = j0 + jj;
                int row = rbase + r;
                float a   = stage[r * 65 + 4 * jj]     + sBias[4 * jj];
                float b   = stage[r * 65 + 4 * jj + 1] + sBias[4 * jj + 1];
                float in_ = stage[r * 65 + 4 * jj + 2] + sBias[4 * jj + 2];
                float hn  = stage[r * 65 + 4 * jj + 3] + sBias[4 * jj + 3];
                float rg = sigm(a), z = sigm(b);
                float ng = ftanh(in_ + rg * hn);
                float hv = h_ens[(size_t)row * H_ + jg];
                float hnew = (1.0f - z) * ng + z * hv;
                float v = hnew * cfac_fast(u_fc1[(size_t)row * H_ + jg], K10, fout);
                O[(size_t)row * 256 + jg] = __float2half_rn(v);
            }
        } else {   // EPI == 4: fused Kalman. cols n0..n0+63 = m (n0/8..n0/8+7)
            int m0 = n0 >> 3;
            for (int i = tid; i < 64 * 8; i += 256) {
                int r = i >> 3, mm = i & 7;
                int m = m0 + mm;
                float acc = 0.0f;
                #pragma unroll
                for (int j = 0; j < 16; j++) acc += sF[m * 16 + j] * sXe[r * 16 + j];
                #pragma unroll
                for (int n = 0; n < 8; n++)
                    acc += (stage[r * 65 + mm * 8 + n] + sBias[mm * 8 + n]) * sInn[r * 8 + n];
                outF[(size_t)(rbase + r) * 16 + m] = acc;
            }
        }
    }
    if (EPI == 3 && (n0 >> 2) == 224) {   // zero hd pad cols 240..255
        f16 zz = __float2half_rn(0.0f);
        for (int i = tid; i < 128 * 16; i += 256)
            O[(size_t)(row0 + (i >> 4)) * 256 + 240 + (i & 15)] = zz;
    }
}

// ---------------------------------------------------------------------------
// k_g1h: grid (8, 512). bx<4: x1 tile -> ch cols 0..239 (guarded);
// bx>=4: h_ens copy (float4 vectorized) -> ch cols 240..479
// ---------------------------------------------------------------------------
__global__ void __launch_bounds__(256) k_g1h(
    const float* __restrict__ feat, const float* __restrict__ u_in,
    const float* __restrict__ p_inp,
    const float* __restrict__ W_in, const float* __restrict__ b_in,
    const float* __restrict__ h_ens,
    f16* __restrict__ C) {
    extern __shared__ char smem[];
    const int tid = threadIdx.x;
    const int row0 = blockIdx.y * 128;

    if (blockIdx.x >= 4) {
        int c0 = (blockIdx.x - 4) * 64;
        for (int i = tid; i < 128 * 16; i += 256) {
            int r = i >> 4, c = c0 + (i & 15) * 4;
            if (c >= 240) continue;
            int row = row0 + r;
            float4 hv = *(const float4*)(h_ens + (size_t)row * H_ + c);
            __half2 p0, p1;
            p0.x = __float2half_rn(hv.x); p0.y = __float2half_rn(hv.y);
            p1.x = __float2half_rn(hv.z); p1.y = __float2half_rn(hv.w);
            f16* op = C + (size_t)row * KC_ + 240 + c;
            *(__half2*)op = p0;
            *(__half2*)(op + 2) = p1;
        }
        return;
    }

    const uint32_t su = smem_u32(smem);
    const int lane = tid & 31;
    const int wm = (tid >> 5) & 3;
    const int wn = tid >> 7;
    const int n0 = blockIdx.x * 64;
    float* sBias = (float*)(smem + 4 * G1PNL);
    if (tid < 64) sBias[tid] = (n0 + tid < 240) ? b_in[n0 + tid] : 0.0f;

    for (int i = tid; i < 64 * 64; i += 256) {
        int n = i >> 6, k = i & 63;
        float w = (n0 + n < 240 && k < IN_) ? W_in[(size_t)(n0 + n) * IN_ + k] : 0.0f;
        uint32_t pb = (k >> 4) * G1PNL + 6144 + n * 48 + (k & 15) * 2;
        *(f16*)(smem + pb) = __float2half_rn(w);
    }
    {
        float plog = *p_inp;
        float finv = 1.0f + __expf(plog);
        float K10 = __expf(10.0f * plog);
        for (int i = tid; i < 128 * 64; i += 256) {
            int r = i >> 6, c = i & 63;
            float v = 0.0f;
            if (c < IN_) {
                int b = (row0 + r) & (B_ - 1);
                v = feat[b * IN_ + c] *
                    cfac_fast(u_in[(size_t)(row0 + r) * IN_ + c], K10, finv);
            }
            uint32_t pb = (c >> 4) * G1PNL + r * 48 + (c & 15) * 2;
            *(f16*)(smem + pb) = __float2half_rn(v);
        }
    }
    __syncthreads();

    float d[2][4][4];
    #pragma unroll
    for (int i = 0; i < 2; i++)
        #pragma unroll
        for (int j = 0; j < 4; j++)
            #pragma unroll
            for (int k = 0; k < 4; k++) d[i][j][k] = 0.0f;
    const uint32_t a_off = (wm * 32 + (lane & 15)) * 48 + (lane >> 4) * 16;
    const uint32_t b_off = (wn * 32 + (lane & 7) + ((lane >> 4) << 3)) * 48 + (((lane >> 3) & 1) << 4);
    #pragma unroll
    for (int p = 0; p < 4; p++) {
        uint32_t pb = su + p * G1PNL;
        uint32_t a[2][4], b[4][2], q[4];
        #pragma unroll
        for (int mt = 0; mt < 2; mt++) ldm4(a[mt], pb + a_off + mt * 768);
        #pragma unroll
        for (int pp = 0; pp < 2; pp++) {
            ldm4(q, pb + 6144 + b_off + pp * 768);
            b[pp * 2][0] = q[0]; b[pp * 2][1] = q[1];
            b[pp * 2 + 1][0] = q[2]; b[pp * 2 + 1][1] = q[3];
        }
        #pragma unroll
        for (int mt = 0; mt < 2; mt++)
            #pragma unroll
            for (int nt = 0; nt < 4; nt++)
                mma16816(d[mt][nt], a[mt], b[nt]);
    }
    __syncthreads();
    float* stage = (float*)smem;
    {
        int lr = lane >> 2, lc = (lane & 3) * 2;
        #pragma unroll
        for (int mt = 0; mt < 2; mt++)
            #pragma unroll
            for (int nt = 0; nt < 4; nt++) {
                int rr = wm * 32 + mt * 16 + lr;
                int cc = wn * 32 + nt * 8 + lc;
                stage[rr * 65 + cc] = d[mt][nt][0];
                stage[rr * 65 + cc + 1] = d[mt][nt][1];
                stage[(rr + 8) * 65 + cc] = d[mt][nt][2];
                stage[(rr + 8) * 65 + cc + 1] = d[mt][nt][3];
            }
    }
    __syncthreads();
    for (int i = tid; i < 128 * 32; i += 256) {
        int r = i >> 5, c = (i & 31) * 2;
        if (n0 + c >= 240) continue;
        float v0 = fmaxf(stage[r * 65 + c] + sBias[c], 0.0f);
        float v1 = fmaxf(stage[r * 65 + c + 1] + sBias[c + 1], 0.0f);
        __half2 pv;
        pv.x = __float2half_rn(v0);
        pv.y = __float2half_rn(v1);
        *(__half2*)(C + (size_t)(row0 + r) * KC_ + n0 + c) = pv;
    }
}

// ---------------- regularizer ----------------
__global__ void k_reg_sums(const float* __restrict__ W_in, const float* __restrict__ W_fc1,
                           const float* __restrict__ W_fc2, double* __restrict__ reg) {
    __shared__ double sd[256];
    int l = blockIdx.x;
    const float* W = (l == 0) ? W_in : (l == 1) ? W_fc1 : W_fc2;
    int n = (l == 0) ? H_ * IN_ : (l == 1) ? O1_ * H_ : M_ * N_ * O1_;
    double s = 0.0;
    for (int i = threadIdx.x; i < n; i += 256) { float w = W[i]; s += (double)w * (double)w; }
    sd[threadIdx.x] = s;
    __syncthreads();
    for (int o = 128; o > 0; o >>= 1) {
        if (threadIdx.x < o) sd[threadIdx.x] += sd[threadIdx.x + o];
        __syncthreads();
    }
    if (threadIdx.x == 0) reg[l] = sd[0];
}
__global__ void k_reg_final(const double* __restrict__ reg, const float* __restrict__ p_in,
                            const float* __restrict__ p_fc1, const float* __restrict__ p_fc2,
                            float* __restrict__ out_reg) {
    double tot = 0.0;
    float pl[3] = {*p_in, *p_fc1, *p_fc2};
    double fan[3] = {(double)IN_, (double)H_, (double)O1_};
    #pragma unroll
    for (int l = 0; l < 3; l++) {
        double p = 1.0 / (1.0 + exp(-(double)pl[l]));
        tot += reg[l] / (1.0 - p) + fan[l] * (p * log(p) + (1.0 - p) * log1p(-p));
    }
    if (threadIdx.x < S_) out_reg[threadIdx.x] = (float)tot;
}

// ---------------- launch ----------------
extern "C" void kernel_launch(void* const* d_in, const int* in_sizes, int n_in,
                              void* d_out, int out_size) {
    const float* y_t    = (const float*)d_in[0];
    const float* x_ens  = (const float*)d_in[1];
    const float* xppm   = (const float*)d_in[2];
    const float* xpdm   = (const float*)d_in[3];
    const float* y_prev = (const float*)d_in[4];
    const float* h_ens  = (const float*)d_in[5];
    const float* F      = (const float*)d_in[6];
    const float* Hm     = (const float*)d_in[7];
    const float* W_in   = (const float*)d_in[8];
    const float* b_in   = (const float*)d_in[9];
    const float* W_ih   = (const float*)d_in[10];
    const float* b_ih   = (const float*)d_in[11];
    const float* W_hh   = (const float*)d_in[12];
    const float* b_hh   = (const float*)d_in[13];
    const float* W_fc1  = (const float*)d_in[14];
    const float* b_fc1  = (const float*)d_in[15];
    const float* W_fc2  = (const float*)d_in[16];
    const float* b_fc2  = (const float*)d_in[17];
    const float* p_in   = (const float*)d_in[18];
    const float* p_fc1  = (const float*)d_in[19];
    const float* p_fc2  = (const float*)d_in[20];
    const float* u_in   = (const float*)d_in[21];
    const float* u_fc1  = (const float*)d_in[22];
    const float* u_fc2  = (const float*)d_in[23];
    float* out = (float*)d_out;

    cudaFuncSetAttribute(mma_gemm<2>, cudaFuncAttributeMaxDynamicSharedMemorySize, SMEM_G);
    cudaFuncSetAttribute(mma_gemm<3>, cudaFuncAttributeMaxDynamicSharedMemorySize, SMEM_G);
    cudaFuncSetAttribute(mma_gemm<4>, cudaFuncAttributeMaxDynamicSharedMemorySize, SMEM_G);
    cudaFuncSetAttribute(k_g1h, cudaFuncAttributeMaxDynamicSharedMemorySize, SMEM_G1);

    float *featp, *innp, *bbp, *bf1p, *bf2p;
    double* regp;
    f16 *ch, *hd, *x2, *wb, *wf1, *wf2;
    cudaGetSymbolAddress((void**)&featp, g_feat);
    cudaGetSymbolAddress((void**)&innp, g_innov);
    cudaGetSymbolAddress((void**)&regp, g_reg);
    cudaGetSymbolAddress((void**)&ch, g_ch);
    cudaGetSymbolAddress((void**)&hd, g_hd);
    cudaGetSymbolAddress((void**)&x2, g_x2);
    cudaGetSymbolAddress((void**)&wb, g_wb);
    cudaGetSymbolAddress((void**)&wf1, g_wf1);
    cudaGetSymbolAddress((void**)&wf2, g_wf2);
    cudaGetSymbolAddress((void**)&bbp, g_bb);
    cudaGetSymbolAddress((void**)&bf1p, g_bf1);
    cudaGetSymbolAddress((void**)&bf2p, g_bf2);

    // merged weight conversion (1 launch replaces 3)
    k_wall<<<(WB_N + WF1_N + WF2_N + 255) / 256, 256>>>(
        W_ih, b_ih, W_hh, b_hh, W_fc1, b_fc1, W_fc2, b_fc2,
        wb, bbp, wf1, bf1p, wf2, bf2p);
    k_prep<<<B_ / 16, 256>>>(y_t, x_ens, xppm, xpdm, y_prev, F, Hm, featp, innp);
    k_g1h<<<dim3(8, ROWS_ / 128), 256, SMEM_G1>>>(featp, u_in, p_in, W_in, b_in, h_ens, ch);
    // fused gi+gh+GRU+dropout -> hd  (K compacted to 480)
    mma_gemm<3><<<dim3(15, ROWS_ / 128), 256, SMEM_G>>>(
        ch, KC_, wb, bbp, nullptr, 0, hd, nullptr, p_fc1, h_ens, u_fc1,
        nullptr, nullptr, nullptr);
    // x2 = cdrop(relu(hd @ W_fc1^T + b_fc1), u_fc2)
    mma_gemm<2><<<dim3(8, ROWS_ / 128), 256, SMEM_G>>>(
        hd, 256, wf1, bf1p, nullptr, 512, x2, u_fc2, p_fc2, nullptr, nullptr,
        nullptr, nullptr, nullptr);
    // Kv = x2 @ W_fc2^T + b_fc2, fused Kalman -> x_filt
    mma_gemm<4><<<dim3(2, ROWS_ / 128), 256, SMEM_G>>>(
        x2, 512, wf2, bf2p, out, 16, nullptr, nullptr, nullptr, nullptr, nullptr,
        x_ens, F, innp);
    k_reg_sums<<<3, 256>>>(W_in, W_fc1, W_fc2, regp);
    k_reg_final<<<1, 32>>>(regp, p_in, p_fc1, p_fc2, out + (size_t)ROWS_ * M_);
}